// round 2
// baseline (speedup 1.0000x reference)
#include <cuda_runtime.h>
#include <math.h>

#define HH 128
#define WW 128
#define NPIX (HH * WW)
#define NPTS 16384
#define KNN 16
#define FDIM 64
#define CAP 12
#define OVFCAP 512

// Output layout (float32, reference-return order):
#define OFF_DEPTH 0
#define OFF_COLOR (NPIX)
#define OFF_FEAT  (NPIX + NPIX * 3)
#define OFF_MASK  (NPIX + NPIX * 3 + NPIX * FDIM)

// ---- device scratch ----
// g_cnt[0..NPIX) = per-cell counters, g_cnt[NPIX] = overflow counter (one memset)
__device__ int    g_cnt[NPIX + 1];
__device__ float4 g_bucket[NPIX * CAP];   // {u, v, z, bitcast(orig_idx)}
__device__ float4 g_ovf[OVFCAP];

__global__ void __launch_bounds__(64) project_bin_kernel(
    const float* __restrict__ pts, const float* __restrict__ intr) {
    int i = blockIdx.x * 64 + threadIdx.x;
    if (i >= NPTS) return;
    float x = pts[3 * i + 0];
    float y = pts[3 * i + 1];
    float z = pts[3 * i + 2];
    float fx = intr[0], cx = intr[2], fy = intr[4], cy = intr[5];
    bool valid = z > 1e-6f;
    float sz = valid ? z : 1.0f;
    float u = __fadd_rn(__fdiv_rn(__fmul_rn(x, fx), sz), cx);
    float v = __fadd_rn(__fdiv_rn(__fmul_rn(y, fy), sz), cy);
    if (!valid) { u = 1e9f; v = 1e9f; }
    if (u > -2.0f && u < 130.0f && v > -2.0f && v < 130.0f) {
        int cu = min(max((int)floorf(u), 0), WW - 1);
        int cv = min(max((int)floorf(v), 0), HH - 1);
        int cell = cv * WW + cu;
        float4 rec = make_float4(u, v, z, __int_as_float(i));
        int pos = atomicAdd(&g_cnt[cell], 1);
        if (pos < CAP) {
            g_bucket[cell * CAP + pos] = rec;
        } else {
            int o = atomicAdd(&g_cnt[NPIX], 1);
            if (o < OVFCAP) g_ovf[o] = rec;
        }
    }
}

__global__ void __launch_bounds__(64) knn_feat_kernel(
    const float* __restrict__ colors, const float* __restrict__ feats,
    float* __restrict__ out) {
    __shared__ float s_w[64][KNN];
    __shared__ int   s_id[64][KNN];
    __shared__ int   s_n[64];

    int tid = threadIdx.x;
    int p = blockIdx.x * 64 + tid;
    int pi = p >> 7;     // row
    int pj = p & 127;    // col
    float px = pj + 0.5f;
    float py = pi + 0.5f;

    float d2s[KNN];
    float zs[KNN];
    int   ids[KNN];
#pragma unroll
    for (int k = 0; k < KNN; ++k) { d2s[k] = 4.0f; ids[k] = -1; zs[k] = 0.0f; }

    int cv0 = max(pi - 2, 0), cv1 = min(pi + 2, HH - 1);
    int cu0 = max(pj - 2, 0), cu1 = min(pj + 2, WW - 1);

    for (int cv = cv0; cv <= cv1; ++cv) {
        for (int cu = cu0; cu <= cu1; ++cu) {
            int cell = cv * WW + cu;
            int cnt = min(g_cnt[cell], CAP);
            const float4* b = &g_bucket[cell * CAP];
            for (int s = 0; s < cnt; ++s) {
                float4 r = b[s];
                float du = __fsub_rn(px, r.x);
                float dv = __fsub_rn(py, r.y);
                float d2 = __fadd_rn(__fmul_rn(du, du), __fmul_rn(dv, dv));
                if (d2 < d2s[KNN - 1]) {
                    d2s[KNN - 1] = d2;
                    zs[KNN - 1] = r.z;
                    ids[KNN - 1] = __float_as_int(r.w);
#pragma unroll
                    for (int k = KNN - 1; k > 0; --k) {
                        if (d2s[k] < d2s[k - 1]) {
                            float td = d2s[k]; d2s[k] = d2s[k - 1]; d2s[k - 1] = td;
                            float tz = zs[k];  zs[k] = zs[k - 1];  zs[k - 1] = tz;
                            int   ti = ids[k]; ids[k] = ids[k - 1]; ids[k - 1] = ti;
                        }
                    }
                }
            }
        }
    }
    // exact overflow handling (normally empty)
    int novf = min(g_cnt[NPIX], OVFCAP);
    for (int s = 0; s < novf; ++s) {
        float4 r = g_ovf[s];
        float du = __fsub_rn(px, r.x);
        float dv = __fsub_rn(py, r.y);
        float d2 = __fadd_rn(__fmul_rn(du, du), __fmul_rn(dv, dv));
        if (d2 < d2s[KNN - 1]) {
            d2s[KNN - 1] = d2;
            zs[KNN - 1] = r.z;
            ids[KNN - 1] = __float_as_int(r.w);
#pragma unroll
            for (int k = KNN - 1; k > 0; --k) {
                if (d2s[k] < d2s[k - 1]) {
                    float td = d2s[k]; d2s[k] = d2s[k - 1]; d2s[k - 1] = td;
                    float tz = zs[k];  zs[k] = zs[k - 1];  zs[k - 1] = tz;
                    int   ti = ids[k]; ids[k] = ids[k - 1]; ids[k - 1] = ti;
                }
            }
        }
    }

    // weights: w = exp(-d2), valid slots are packed at front (ascending d2)
    float w[KNN];
    float wsum = 0.0f;
    int nvalid = 0;
#pragma unroll
    for (int k = 0; k < KNN; ++k) {
        bool ok = (ids[k] >= 0);
        float wk = ok ? expf(-d2s[k]) : 0.0f;
        w[k] = wk;
        wsum += wk;
        nvalid += ok ? 1 : 0;
    }
    float winv = 1.0f / (wsum + 1e-10f);

    float dsum = 0.0f;
    float c0 = 0.0f, c1 = 0.0f, c2 = 0.0f;
#pragma unroll
    for (int k = 0; k < KNN; ++k) {
        float wn = w[k] * winv;
        int oi = (ids[k] >= 0) ? ids[k] : 0;
        dsum += zs[k] * wn;
        if (ids[k] >= 0) {
            c0 += colors[3 * oi + 0] * wn;
            c1 += colors[3 * oi + 1] * wn;
            c2 += colors[3 * oi + 2] * wn;
        }
        s_w[tid][k] = wn;
        s_id[tid][k] = oi;
    }
    s_n[tid] = nvalid;

    out[OFF_DEPTH + p] = dsum;
    out[OFF_COLOR + 3 * p + 0] = c0;
    out[OFF_COLOR + 3 * p + 1] = c1;
    out[OFF_COLOR + 3 * p + 2] = c2;
    out[OFF_MASK + p] = (nvalid > 0) ? 1.0f : 0.0f;

    __syncthreads();

    // ---- feature phase: warp per pixel, lane = feature dim ----
    int warp = tid >> 5;
    int lane = tid & 31;
    for (int t = 0; t < 32; ++t) {
        int lp = warp * 32 + t;
        int n = s_n[lp];
        float a0 = 0.0f, a1 = 0.0f;
        for (int k = 0; k < n; ++k) {
            float wk = s_w[lp][k];
            int id = s_id[lp][k];
            const float* f = feats + (size_t)id * FDIM;
            a0 += wk * f[lane];
            a1 += wk * f[lane + 32];
        }
        size_t gp = (size_t)blockIdx.x * 64 + lp;
        out[OFF_FEAT + gp * FDIM + lane] = a0;
        out[OFF_FEAT + gp * FDIM + lane + 32] = a1;
    }
}

extern "C" void kernel_launch(void* const* d_in, const int* in_sizes, int n_in,
                              void* d_out, int out_size) {
    const float* pts    = (const float*)d_in[0];  // (N,3)
    const float* colors = (const float*)d_in[1];  // (N,3)
    const float* feats  = (const float*)d_in[2];  // (N,64)
    const float* intr   = (const float*)d_in[3];  // (3,3)
    float* out = (float*)d_out;

    void* p_cnt = nullptr;
    cudaGetSymbolAddress(&p_cnt, g_cnt);
    cudaMemsetAsync(p_cnt, 0, sizeof(int) * (NPIX + 1), 0);

    project_bin_kernel<<<NPTS / 64, 64>>>(pts, intr);
    knn_feat_kernel<<<NPIX / 64, 64>>>(colors, feats, out);
}

// round 3
// speedup vs baseline: 1.4639x; 1.4639x over previous
#include <cuda_runtime.h>
#include <math.h>

#define HH 128
#define WW 128
#define NPIX (HH * WW)
#define NPTS 16384
#define KNN 16
#define FDIM 64
#define CAP 12
#define OVFCAP 512

#define OFF_DEPTH 0
#define OFF_COLOR (NPIX)
#define OFF_FEAT  (NPIX + NPIX * 3)
#define OFF_MASK  (NPIX + NPIX * 3 + NPIX * FDIM)

// ---- device scratch ----
__device__ int    g_cnt[NPIX + 1];        // per-cell counts + overflow counter
__device__ float4 g_bucket[NPIX * CAP];   // {u, v, z, bitcast(idx)}
__device__ float4 g_ovf[OVFCAP];
__device__ float  g_w[NPIX * KNN];        // normalized weights
__device__ int    g_i[NPIX * KNN];        // original point indices
__device__ int    g_n[NPIX];              // valid count per pixel

__global__ void __launch_bounds__(64) project_bin_kernel(
    const float* __restrict__ pts, const float* __restrict__ intr) {
    int i = blockIdx.x * 64 + threadIdx.x;
    if (i >= NPTS) return;
    float x = pts[3 * i + 0];
    float y = pts[3 * i + 1];
    float z = pts[3 * i + 2];
    float fx = intr[0], cx = intr[2], fy = intr[4], cy = intr[5];
    bool valid = z > 1e-6f;
    float sz = valid ? z : 1.0f;
    float u = __fadd_rn(__fdiv_rn(__fmul_rn(x, fx), sz), cx);
    float v = __fadd_rn(__fdiv_rn(__fmul_rn(y, fy), sz), cy);
    if (!valid) { u = 1e9f; v = 1e9f; }
    if (u > -2.0f && u < 130.0f && v > -2.0f && v < 130.0f) {
        int cu = min(max((int)floorf(u), 0), WW - 1);
        int cv = min(max((int)floorf(v), 0), HH - 1);
        int cell = cv * WW + cu;
        float4 rec = make_float4(u, v, z, __int_as_float(i));
        int pos = atomicAdd(&g_cnt[cell], 1);
        if (pos < CAP) {
            g_bucket[cell * CAP + pos] = rec;
        } else {
            int o = atomicAdd(&g_cnt[NPIX], 1);
            if (o < OVFCAP) g_ovf[o] = rec;
        }
    }
}

// per-pixel candidate list in shared memory, [slot][tid] layout -> no bank conflicts
__global__ void __launch_bounds__(64) knn_kernel(
    const float* __restrict__ colors, float* __restrict__ out) {
    __shared__ float s_d2[KNN * 64];
    __shared__ float s_z [KNN * 64];
    __shared__ int   s_id[KNN * 64];

    int tid = threadIdx.x;
    int p = blockIdx.x * 64 + tid;
    int pi = p >> 7;
    int pj = p & 127;
    float px = pj + 0.5f;
    float py = pi + 0.5f;

    int n = 0;
    float curmax = -1.0f;
    int argmax = 0;

    int cv0 = max(pi - 2, 0), cv1 = min(pi + 2, HH - 1);
    int cu0 = max(pj - 2, 0), cu1 = min(pj + 2, WW - 1);
    int novf = min(g_cnt[NPIX], OVFCAP);

    for (int cv = cv0; cv <= cv1 + 1; ++cv) {
        bool ovfpass = (cv == cv1 + 1);
        int cu_lo = ovfpass ? 0 : cu0;
        int cu_hi = ovfpass ? 0 : cu1;
        for (int cu = cu_lo; cu <= cu_hi; ++cu) {
            int cnt;
            const float4* b;
            if (ovfpass) {
                cnt = novf;
                b = g_ovf;
            } else {
                int cell = cv * WW + cu;
                cnt = min(g_cnt[cell], CAP);
                b = &g_bucket[cell * CAP];
            }
            for (int s = 0; s < cnt; ++s) {
                float4 r = b[s];
                float du = __fsub_rn(px, r.x);
                float dv = __fsub_rn(py, r.y);
                float d2 = __fadd_rn(__fmul_rn(du, du), __fmul_rn(dv, dv));
                if (d2 >= 4.0f) continue;
                if (n < KNN) {
                    s_d2[n * 64 + tid] = d2;
                    s_z [n * 64 + tid] = r.z;
                    s_id[n * 64 + tid] = __float_as_int(r.w);
                    if (d2 > curmax) { curmax = d2; argmax = n; }
                    ++n;
                } else if (d2 < curmax) {
                    s_d2[argmax * 64 + tid] = d2;
                    s_z [argmax * 64 + tid] = r.z;
                    s_id[argmax * 64 + tid] = __float_as_int(r.w);
                    // rescan for new max (rare)
                    curmax = -1.0f;
#pragma unroll
                    for (int k = 0; k < KNN; ++k) {
                        float dk = s_d2[k * 64 + tid];
                        if (dk > curmax) { curmax = dk; argmax = k; }
                    }
                }
            }
        }
    }

    // weights
    float wsum = 0.0f;
    for (int k = 0; k < n; ++k) {
        float wk = __expf(-s_d2[k * 64 + tid]);
        s_d2[k * 64 + tid] = wk;   // reuse slot for weight
        wsum += wk;
    }
    float winv = 1.0f / (wsum + 1e-10f);

    float dsum = 0.0f, c0 = 0.0f, c1 = 0.0f, c2 = 0.0f;
    for (int k = 0; k < n; ++k) {
        float wn = s_d2[k * 64 + tid] * winv;
        int oi = s_id[k * 64 + tid];
        dsum += s_z[k * 64 + tid] * wn;
        c0 += __ldg(&colors[3 * oi + 0]) * wn;
        c1 += __ldg(&colors[3 * oi + 1]) * wn;
        c2 += __ldg(&colors[3 * oi + 2]) * wn;
        g_w[p * KNN + k] = wn;
        g_i[p * KNN + k] = oi;
    }
    g_n[p] = n;

    out[OFF_DEPTH + p] = dsum;
    out[OFF_COLOR + 3 * p + 0] = c0;
    out[OFF_COLOR + 3 * p + 1] = c1;
    out[OFF_COLOR + 3 * p + 2] = c2;
    out[OFF_MASK + p] = (n > 0) ? 1.0f : 0.0f;
}

// warp per pixel, lane = feature dim
__global__ void __launch_bounds__(256) feat_kernel(
    const float* __restrict__ feats, float* __restrict__ out) {
    int p = blockIdx.x * 8 + (threadIdx.x >> 5);
    int lane = threadIdx.x & 31;
    int n = g_n[p];
    float a0 = 0.0f, a1 = 0.0f;
    for (int k = 0; k < n; ++k) {
        float wk = g_w[p * KNN + k];       // warp-uniform broadcast
        int id = g_i[p * KNN + k];
        const float* f = feats + (size_t)id * FDIM;
        a0 += wk * __ldg(&f[lane]);
        a1 += wk * __ldg(&f[lane + 32]);
    }
    out[OFF_FEAT + (size_t)p * FDIM + lane] = a0;
    out[OFF_FEAT + (size_t)p * FDIM + lane + 32] = a1;
}

extern "C" void kernel_launch(void* const* d_in, const int* in_sizes, int n_in,
                              void* d_out, int out_size) {
    const float* pts    = (const float*)d_in[0];
    const float* colors = (const float*)d_in[1];
    const float* feats  = (const float*)d_in[2];
    const float* intr   = (const float*)d_in[3];
    float* out = (float*)d_out;

    void* p_cnt = nullptr;
    cudaGetSymbolAddress(&p_cnt, g_cnt);
    cudaMemsetAsync(p_cnt, 0, sizeof(int) * (NPIX + 1), 0);

    project_bin_kernel<<<NPTS / 64, 64>>>(pts, intr);
    knn_kernel<<<NPIX / 64, 64>>>(colors, out);
    feat_kernel<<<NPIX / 8, 256>>>(feats, out);
}

// round 5
// speedup vs baseline: 2.6192x; 1.7892x over previous
#include <cuda_runtime.h>
#include <math.h>

#define HH 128
#define WW 128
#define NPIX (HH * WW)
#define NPTS 16384
#define KNN 16
#define FDIM 64
#define CAP 12
#define OVFCAP 512
#define FULLMASK 0xffffffffu

#define OFF_DEPTH 0
#define OFF_COLOR (NPIX)
#define OFF_FEAT  (NPIX + NPIX * 3)
#define OFF_MASK  (NPIX + NPIX * 3 + NPIX * FDIM)

// ---- device scratch ----
__device__ int    g_cnt[NPIX + 1];        // per-cell counts + overflow counter
__device__ float4 g_bucket[NPIX * CAP];   // {u, v, z, bitcast(idx)}
__device__ float4 g_ovf[OVFCAP];

__global__ void __launch_bounds__(256) project_bin_kernel(
    const float* __restrict__ pts, const float* __restrict__ intr) {
    int i = blockIdx.x * 256 + threadIdx.x;
    if (i >= NPTS) return;
    float x = __ldg(&pts[3 * i + 0]);
    float y = __ldg(&pts[3 * i + 1]);
    float z = __ldg(&pts[3 * i + 2]);
    float fx = intr[0], cx = intr[2], fy = intr[4], cy = intr[5];
    bool valid = z > 1e-6f;
    float sz = valid ? z : 1.0f;
    float u = __fadd_rn(__fdiv_rn(__fmul_rn(x, fx), sz), cx);
    float v = __fadd_rn(__fdiv_rn(__fmul_rn(y, fy), sz), cy);
    if (!valid) { u = 1e9f; v = 1e9f; }
    if (u > -2.0f && u < 130.0f && v > -2.0f && v < 130.0f) {
        int cu = min(max((int)floorf(u), 0), WW - 1);
        int cv = min(max((int)floorf(v), 0), HH - 1);
        int cell = cv * WW + cu;
        float4 rec = make_float4(u, v, z, __int_as_float(i));
        int pos = atomicAdd(&g_cnt[cell], 1);
        if (pos < CAP) {
            g_bucket[cell * CAP + pos] = rec;
        } else {
            int o = atomicAdd(&g_cnt[NPIX], 1);
            if (o < OVFCAP) g_ovf[o] = rec;
        }
    }
}

// convergent warp binary search: last lane l with excl_l <= j
// MUST be called by all 32 lanes with no divergence.
__device__ __forceinline__ int bsearch_lane(int excl, int j) {
    int lo = 0;
#pragma unroll
    for (int step = 16; step; step >>= 1) {
        int cand = min(lo + step, 31);
        int v = __shfl_sync(FULLMASK, excl, cand);
        if ((lo + step) <= 31 && v <= j) lo = lo + step;
    }
    return lo;
}

// warp per pixel: 16384 warps, 2048 blocks x 256
__global__ void __launch_bounds__(256) knn_feat_kernel(
    const float* __restrict__ colors, const float* __restrict__ feats,
    float* __restrict__ out) {
    __shared__ float s_fw[8][KNN];
    __shared__ int   s_fi[8][KNN];
    __shared__ int   s_fn[8];

    int lane = threadIdx.x & 31;
    int warp = threadIdx.x >> 5;
    int p = blockIdx.x * 8 + warp;
    int pi = p >> 7, pj = p & 127;
    float px = pj + 0.5f, py = pi + 0.5f;

    // lane -> neighbor cell (5x5)
    int rr = lane / 5, qq = lane - 5 * rr;
    int cv = pi - 2 + rr, cu = pj - 2 + qq;
    bool cok = (lane < 25) && (cv >= 0) && (cv < HH) && (cu >= 0) && (cu < WW);
    int cell = cok ? (cv * WW + cu) : 0;
    int cnt = cok ? min(g_cnt[cell], CAP) : 0;

    // warp inclusive scan of counts
    int incl = cnt;
#pragma unroll
    for (int o = 1; o < 32; o <<= 1) {
        int v = __shfl_up_sync(FULLMASK, incl, o);
        if (lane >= o) incl += v;
    }
    int T = __shfl_sync(FULLMASK, incl, 31);
    int excl = incl - cnt;
    int novf = g_cnt[NPIX];

    float wn0 = 0.0f, wn1 = 0.0f;
    int id0 = 0, id1 = 0;
    unsigned ball0 = 0, ball1 = 0;
    bool fastpath = (T <= 64) && (novf == 0);

    float dsum = 0.0f, c0s = 0.0f, c1s = 0.0f, c2s = 0.0f;
    int anyok = 0;

    if (fastpath) {
        float d2_0 = 4.0f, d2_1 = 4.0f, z0 = 0.0f, z1 = 0.0f;
        bool act0 = false, act1 = false;

        // batch 0: candidate j = lane  (all warp-collectives convergent)
        {
            int j = lane;
            int l = bsearch_lane(excl, j);           // convergent
            int cl = __shfl_sync(FULLMASK, cell, l); // convergent
            int eo = __shfl_sync(FULLMASK, excl, l); // convergent
            if (j < T) {                             // only the load is predicated
                float4 rec = g_bucket[cl * CAP + (j - eo)];
                float du = __fsub_rn(px, rec.x);
                float dv = __fsub_rn(py, rec.y);
                float d2 = __fadd_rn(__fmul_rn(du, du), __fmul_rn(dv, dv));
                if (d2 < 4.0f) { act0 = true; d2_0 = d2; z0 = rec.z; id0 = __float_as_int(rec.w); }
            }
        }
        // batch 1: candidate j = lane + 32 (uniform guard: T is warp-uniform)
        if (T > 32) {
            int j = lane + 32;
            int l = bsearch_lane(excl, j);
            int cl = __shfl_sync(FULLMASK, cell, l);
            int eo = __shfl_sync(FULLMASK, excl, l);
            if (j < T) {
                float4 rec = g_bucket[cl * CAP + (j - eo)];
                float du = __fsub_rn(px, rec.x);
                float dv = __fsub_rn(py, rec.y);
                float d2 = __fadd_rn(__fmul_rn(du, du), __fmul_rn(dv, dv));
                if (d2 < 4.0f) { act1 = true; d2_1 = d2; z1 = rec.z; id1 = __float_as_int(rec.w); }
            }
        }

        // exact top-16 eviction (rare: m > 16); loop condition is warp-uniform
        int m = __popc(__ballot_sync(FULLMASK, act0)) + __popc(__ballot_sync(FULLMASK, act1));
        while (m > KNN) {
            float lm = -1.0f;
            if (act0) lm = d2_0;
            if (act1 && d2_1 > lm) lm = d2_1;
            float gm = lm;
#pragma unroll
            for (int o = 16; o; o >>= 1)
                gm = fmaxf(gm, __shfl_xor_sync(FULLMASK, gm, o));
            unsigned v1 = __ballot_sync(FULLMASK, act1 && d2_1 == gm);
            unsigned v0 = __ballot_sync(FULLMASK, act0 && d2_0 == gm);
            if (v1) { if (lane == 31 - __clz(v1)) act1 = false; }
            else    { if (lane == 31 - __clz(v0)) act0 = false; }
            --m;
        }

        // weights + blend reductions
        float w0 = act0 ? __expf(-d2_0) : 0.0f;
        float w1 = act1 ? __expf(-d2_1) : 0.0f;
        float ws = w0 + w1;
        float wz = w0 * z0 + w1 * z1;
        float wc0 = 0.0f, wc1 = 0.0f, wc2 = 0.0f;
        if (act0) {
            wc0 = w0 * __ldg(&colors[3 * id0 + 0]);
            wc1 = w0 * __ldg(&colors[3 * id0 + 1]);
            wc2 = w0 * __ldg(&colors[3 * id0 + 2]);
        }
        if (act1) {
            wc0 += w1 * __ldg(&colors[3 * id1 + 0]);
            wc1 += w1 * __ldg(&colors[3 * id1 + 1]);
            wc2 += w1 * __ldg(&colors[3 * id1 + 2]);
        }
#pragma unroll
        for (int o = 16; o; o >>= 1) {
            ws  += __shfl_xor_sync(FULLMASK, ws, o);
            wz  += __shfl_xor_sync(FULLMASK, wz, o);
            wc0 += __shfl_xor_sync(FULLMASK, wc0, o);
            wc1 += __shfl_xor_sync(FULLMASK, wc1, o);
            wc2 += __shfl_xor_sync(FULLMASK, wc2, o);
        }
        float winv = 1.0f / (ws + 1e-10f);
        dsum = wz * winv;
        c0s = wc0 * winv; c1s = wc1 * winv; c2s = wc2 * winv;
        wn0 = w0 * winv;  wn1 = w1 * winv;
        ball0 = __ballot_sync(FULLMASK, act0);
        ball1 = __ballot_sync(FULLMASK, act1);
        anyok = (ball0 | ball1) ? 1 : 0;
    } else {
        // exact scalar fallback (lane 0); path condition is warp-uniform
        if (lane == 0) {
            float d2s[KNN], zs[KNN];
            int ids[KNN];
            int n = 0;
            float curmax = -1.0f;
            int argmax = 0;
            int cv0 = max(pi - 2, 0), cv1 = min(pi + 2, HH - 1);
            int cu0 = max(pj - 2, 0), cu1 = min(pj + 2, WW - 1);
            int no = min(novf, OVFCAP);
            for (int a = cv0; a <= cv1 + 1; ++a) {
                bool op = (a == cv1 + 1);
                int blo = op ? 0 : cu0, bhi = op ? 0 : cu1;
                for (int b = blo; b <= bhi; ++b) {
                    int cc;
                    const float4* bk;
                    if (op) { cc = no; bk = g_ovf; }
                    else { int ce = a * WW + b; cc = min(g_cnt[ce], CAP); bk = &g_bucket[ce * CAP]; }
                    for (int s = 0; s < cc; ++s) {
                        float4 rec = bk[s];
                        float du = __fsub_rn(px, rec.x);
                        float dv = __fsub_rn(py, rec.y);
                        float d2 = __fadd_rn(__fmul_rn(du, du), __fmul_rn(dv, dv));
                        if (d2 >= 4.0f) continue;
                        if (n < KNN) {
                            d2s[n] = d2; zs[n] = rec.z; ids[n] = __float_as_int(rec.w);
                            if (d2 > curmax) { curmax = d2; argmax = n; }
                            ++n;
                        } else if (d2 < curmax) {
                            d2s[argmax] = d2; zs[argmax] = rec.z; ids[argmax] = __float_as_int(rec.w);
                            curmax = -1.0f;
                            for (int k = 0; k < KNN; ++k)
                                if (d2s[k] > curmax) { curmax = d2s[k]; argmax = k; }
                        }
                    }
                }
            }
            float ws = 0.0f;
            for (int k = 0; k < n; ++k) { d2s[k] = __expf(-d2s[k]); ws += d2s[k]; }
            float winv = 1.0f / (ws + 1e-10f);
            float ds = 0.0f, a0 = 0.0f, a1 = 0.0f, a2 = 0.0f;
            for (int k = 0; k < n; ++k) {
                float wn = d2s[k] * winv;
                int oi = ids[k];
                ds += zs[k] * wn;
                a0 += __ldg(&colors[3 * oi + 0]) * wn;
                a1 += __ldg(&colors[3 * oi + 1]) * wn;
                a2 += __ldg(&colors[3 * oi + 2]) * wn;
                s_fw[warp][k] = wn;
                s_fi[warp][k] = oi;
            }
            s_fn[warp] = n;
            out[OFF_DEPTH + p] = ds;
            out[OFF_COLOR + 3 * p + 0] = a0;
            out[OFF_COLOR + 3 * p + 1] = a1;
            out[OFF_COLOR + 3 * p + 2] = a2;
            out[OFF_MASK + p] = (n > 0) ? 1.0f : 0.0f;
        }
        __syncwarp();
    }

    // feature gather: lane = dim; masks m0/m1 are warp-uniform -> uniform branches
    float fa0 = 0.0f, fa1 = 0.0f, fb0 = 0.0f, fb1 = 0.0f;
    if (fastpath) {
        unsigned m0 = ball0, m1 = ball1;
        while (m0 | m1) {
            if (m0) {
                int b = __ffs(m0) - 1; m0 &= m0 - 1;
                float wn = __shfl_sync(FULLMASK, wn0, b);
                int id = __shfl_sync(FULLMASK, id0, b);
                const float* f = feats + (size_t)id * FDIM;
                fa0 += wn * __ldg(f + lane);
                fa1 += wn * __ldg(f + lane + 32);
            }
            if (m1) {
                int b = __ffs(m1) - 1; m1 &= m1 - 1;
                float wn = __shfl_sync(FULLMASK, wn1, b);
                int id = __shfl_sync(FULLMASK, id1, b);
                const float* f = feats + (size_t)id * FDIM;
                fb0 += wn * __ldg(f + lane);
                fb1 += wn * __ldg(f + lane + 32);
            }
        }
    } else {
        int n = s_fn[warp];
        for (int k = 0; k < n; ++k) {
            float wn = s_fw[warp][k];
            int id = s_fi[warp][k];
            const float* f = feats + (size_t)id * FDIM;
            fa0 += wn * __ldg(f + lane);
            fa1 += wn * __ldg(f + lane + 32);
        }
    }
    out[OFF_FEAT + (size_t)p * FDIM + lane] = fa0 + fb0;
    out[OFF_FEAT + (size_t)p * FDIM + lane + 32] = fa1 + fb1;

    if (fastpath && lane == 0) {
        out[OFF_DEPTH + p] = dsum;
        out[OFF_COLOR + 3 * p + 0] = c0s;
        out[OFF_COLOR + 3 * p + 1] = c1s;
        out[OFF_COLOR + 3 * p + 2] = c2s;
        out[OFF_MASK + p] = anyok ? 1.0f : 0.0f;
    }
}

extern "C" void kernel_launch(void* const* d_in, const int* in_sizes, int n_in,
                              void* d_out, int out_size) {
    const float* pts    = (const float*)d_in[0];
    const float* colors = (const float*)d_in[1];
    const float* feats  = (const float*)d_in[2];
    const float* intr   = (const float*)d_in[3];
    float* out = (float*)d_out;

    void* p_cnt = nullptr;
    cudaGetSymbolAddress(&p_cnt, g_cnt);
    cudaMemsetAsync(p_cnt, 0, sizeof(int) * (NPIX + 1), 0);

    project_bin_kernel<<<NPTS / 256, 256>>>(pts, intr);
    knn_feat_kernel<<<NPIX / 8, 256>>>(colors, feats, out);
}

// round 6
// speedup vs baseline: 3.0439x; 1.1622x over previous
#include <cuda_runtime.h>
#include <math.h>

#define HH 128
#define WW 128
#define NPIX (HH * WW)
#define NPTS 16384
#define KNN 16
#define FDIM 64
#define CAP 12
#define OVFCAP 512
#define FULLMASK 0xffffffffu

#define OFF_DEPTH 0
#define OFF_COLOR (NPIX)
#define OFF_FEAT  (NPIX + NPIX * 3)
#define OFF_MASK  (NPIX + NPIX * 3 + NPIX * FDIM)

// ---- device scratch ----
__device__ int    g_cnt[NPIX + 1];
__device__ float4 g_bucket[NPIX * CAP];
__device__ float4 g_ovf[OVFCAP];

__global__ void __launch_bounds__(256) project_bin_kernel(
    const float* __restrict__ pts, const float* __restrict__ intr) {
    int i = blockIdx.x * 256 + threadIdx.x;
    if (i >= NPTS) return;
    float x = __ldg(&pts[3 * i + 0]);
    float y = __ldg(&pts[3 * i + 1]);
    float z = __ldg(&pts[3 * i + 2]);
    float fx = intr[0], cx = intr[2], fy = intr[4], cy = intr[5];
    bool valid = z > 1e-6f;
    float sz = valid ? z : 1.0f;
    float u = __fadd_rn(__fdiv_rn(__fmul_rn(x, fx), sz), cx);
    float v = __fadd_rn(__fdiv_rn(__fmul_rn(y, fy), sz), cy);
    if (!valid) { u = 1e9f; v = 1e9f; }
    if (u > -2.0f && u < 130.0f && v > -2.0f && v < 130.0f) {
        int cu = min(max((int)floorf(u), 0), WW - 1);
        int cv = min(max((int)floorf(v), 0), HH - 1);
        int cell = cv * WW + cu;
        float4 rec = make_float4(u, v, z, __int_as_float(i));
        int pos = atomicAdd(&g_cnt[cell], 1);
        if (pos < CAP) {
            g_bucket[cell * CAP + pos] = rec;
        } else {
            int o = atomicAdd(&g_cnt[NPIX], 1);
            if (o < OVFCAP) g_ovf[o] = rec;
        }
    }
}

// convergent warp binary search: last lane l with excl_l <= j
__device__ __forceinline__ int bsearch_lane(int excl, int j) {
    int lo = 0;
#pragma unroll
    for (int step = 16; step; step >>= 1) {
        int cand = min(lo + step, 31);
        int v = __shfl_sync(FULLMASK, excl, cand);
        if ((lo + step) <= 31 && v <= j) lo = lo + step;
    }
    return lo;
}

// warp per pixel: 16384 warps, 2048 blocks x 256
__global__ void __launch_bounds__(256) knn_feat_kernel(
    const float* __restrict__ colors, const float* __restrict__ feats,
    float* __restrict__ out) {
    __shared__ float2 s_c[8][KNN];   // compacted {wn, bitcast(id)} per pixel
    __shared__ int    s_fn[8];

    int lane = threadIdx.x & 31;
    int warp = threadIdx.x >> 5;
    int p = blockIdx.x * 8 + warp;
    int pi = p >> 7, pj = p & 127;
    float px = pj + 0.5f, py = pi + 0.5f;

    // lane -> neighbor cell (5x5)
    int rr = lane / 5, qq = lane - 5 * rr;
    int cv = pi - 2 + rr, cu = pj - 2 + qq;
    bool cok = (lane < 25) && (cv >= 0) && (cv < HH) && (cu >= 0) && (cu < WW);
    int cell = cok ? (cv * WW + cu) : 0;
    int cnt = cok ? min(g_cnt[cell], CAP) : 0;

    // warp inclusive scan of counts
    int incl = cnt;
#pragma unroll
    for (int o = 1; o < 32; o <<= 1) {
        int v = __shfl_up_sync(FULLMASK, incl, o);
        if (lane >= o) incl += v;
    }
    int T = __shfl_sync(FULLMASK, incl, 31);
    int excl = incl - cnt;
    int novf = g_cnt[NPIX];

    bool fastpath = (T <= 64) && (novf == 0);
    unsigned lmask = (1u << lane) - 1u;

    float dsum = 0.0f, c0s = 0.0f, c1s = 0.0f, c2s = 0.0f;
    int anyok = 0;

    if (fastpath) {
        float d2_0 = 4.0f, d2_1 = 4.0f, z0 = 0.0f, z1 = 0.0f;
        int id0 = 0, id1 = 0;
        bool act0 = false, act1 = false;

        // batch 0: candidate j = lane (warp-collectives convergent)
        {
            int j = lane;
            int l = bsearch_lane(excl, j);
            int cl = __shfl_sync(FULLMASK, cell, l);
            int eo = __shfl_sync(FULLMASK, excl, l);
            if (j < T) {
                float4 rec = g_bucket[cl * CAP + (j - eo)];
                float du = __fsub_rn(px, rec.x);
                float dv = __fsub_rn(py, rec.y);
                float d2 = __fadd_rn(__fmul_rn(du, du), __fmul_rn(dv, dv));
                if (d2 < 4.0f) { act0 = true; d2_0 = d2; z0 = rec.z; id0 = __float_as_int(rec.w); }
            }
        }
        // batch 1: candidate j = lane + 32 (uniform guard)
        if (T > 32) {
            int j = lane + 32;
            int l = bsearch_lane(excl, j);
            int cl = __shfl_sync(FULLMASK, cell, l);
            int eo = __shfl_sync(FULLMASK, excl, l);
            if (j < T) {
                float4 rec = g_bucket[cl * CAP + (j - eo)];
                float du = __fsub_rn(px, rec.x);
                float dv = __fsub_rn(py, rec.y);
                float d2 = __fadd_rn(__fmul_rn(du, du), __fmul_rn(dv, dv));
                if (d2 < 4.0f) { act1 = true; d2_1 = d2; z1 = rec.z; id1 = __float_as_int(rec.w); }
            }
        }

        // exact top-16 eviction (rare)
        int m = __popc(__ballot_sync(FULLMASK, act0)) + __popc(__ballot_sync(FULLMASK, act1));
        while (m > KNN) {
            float lm = -1.0f;
            if (act0) lm = d2_0;
            if (act1 && d2_1 > lm) lm = d2_1;
            float gm = lm;
#pragma unroll
            for (int o = 16; o; o >>= 1)
                gm = fmaxf(gm, __shfl_xor_sync(FULLMASK, gm, o));
            unsigned v1 = __ballot_sync(FULLMASK, act1 && d2_1 == gm);
            unsigned v0 = __ballot_sync(FULLMASK, act0 && d2_0 == gm);
            if (v1) { if (lane == 31 - __clz(v1)) act1 = false; }
            else    { if (lane == 31 - __clz(v0)) act0 = false; }
            --m;
        }

        // weights + blend reductions
        float w0 = act0 ? __expf(-d2_0) : 0.0f;
        float w1 = act1 ? __expf(-d2_1) : 0.0f;
        float ws = w0 + w1;
        float wz = w0 * z0 + w1 * z1;
        float wc0 = 0.0f, wc1 = 0.0f, wc2 = 0.0f;
        if (act0) {
            wc0 = w0 * __ldg(&colors[3 * id0 + 0]);
            wc1 = w0 * __ldg(&colors[3 * id0 + 1]);
            wc2 = w0 * __ldg(&colors[3 * id0 + 2]);
        }
        if (act1) {
            wc0 += w1 * __ldg(&colors[3 * id1 + 0]);
            wc1 += w1 * __ldg(&colors[3 * id1 + 1]);
            wc2 += w1 * __ldg(&colors[3 * id1 + 2]);
        }
#pragma unroll
        for (int o = 16; o; o >>= 1) {
            ws  += __shfl_xor_sync(FULLMASK, ws, o);
            wz  += __shfl_xor_sync(FULLMASK, wz, o);
            wc0 += __shfl_xor_sync(FULLMASK, wc0, o);
            wc1 += __shfl_xor_sync(FULLMASK, wc1, o);
            wc2 += __shfl_xor_sync(FULLMASK, wc2, o);
        }
        float winv = 1.0f / (ws + 1e-10f);
        dsum = wz * winv;
        c0s = wc0 * winv; c1s = wc1 * winv; c2s = wc2 * winv;

        // compact contributing candidates into smem: {wn, id}
        unsigned ball0 = __ballot_sync(FULLMASK, act0);
        unsigned ball1 = __ballot_sync(FULLMASK, act1);
        int n0 = __popc(ball0);
        if (act0) s_c[warp][__popc(ball0 & lmask)] = make_float2(w0 * winv, __int_as_float(id0));
        if (act1) s_c[warp][n0 + __popc(ball1 & lmask)] = make_float2(w1 * winv, __int_as_float(id1));
        if (lane == 0) s_fn[warp] = n0 + __popc(ball1);
        anyok = (ball0 | ball1) ? 1 : 0;
    } else {
        // exact scalar fallback (lane 0); warp-uniform path condition
        if (lane == 0) {
            float d2s[KNN], zs[KNN];
            int ids[KNN];
            int n = 0;
            float curmax = -1.0f;
            int argmax = 0;
            int cv0 = max(pi - 2, 0), cv1 = min(pi + 2, HH - 1);
            int cu0 = max(pj - 2, 0), cu1 = min(pj + 2, WW - 1);
            int no = min(novf, OVFCAP);
            for (int a = cv0; a <= cv1 + 1; ++a) {
                bool op = (a == cv1 + 1);
                int blo = op ? 0 : cu0, bhi = op ? 0 : cu1;
                for (int b = blo; b <= bhi; ++b) {
                    int cc;
                    const float4* bk;
                    if (op) { cc = no; bk = g_ovf; }
                    else { int ce = a * WW + b; cc = min(g_cnt[ce], CAP); bk = &g_bucket[ce * CAP]; }
                    for (int s = 0; s < cc; ++s) {
                        float4 rec = bk[s];
                        float du = __fsub_rn(px, rec.x);
                        float dv = __fsub_rn(py, rec.y);
                        float d2 = __fadd_rn(__fmul_rn(du, du), __fmul_rn(dv, dv));
                        if (d2 >= 4.0f) continue;
                        if (n < KNN) {
                            d2s[n] = d2; zs[n] = rec.z; ids[n] = __float_as_int(rec.w);
                            if (d2 > curmax) { curmax = d2; argmax = n; }
                            ++n;
                        } else if (d2 < curmax) {
                            d2s[argmax] = d2; zs[argmax] = rec.z; ids[argmax] = __float_as_int(rec.w);
                            curmax = -1.0f;
                            for (int k = 0; k < KNN; ++k)
                                if (d2s[k] > curmax) { curmax = d2s[k]; argmax = k; }
                        }
                    }
                }
            }
            float ws = 0.0f;
            for (int k = 0; k < n; ++k) { d2s[k] = __expf(-d2s[k]); ws += d2s[k]; }
            float winv = 1.0f / (ws + 1e-10f);
            float ds = 0.0f, a0 = 0.0f, a1 = 0.0f, a2 = 0.0f;
            for (int k = 0; k < n; ++k) {
                float wn = d2s[k] * winv;
                int oi = ids[k];
                ds += zs[k] * wn;
                a0 += __ldg(&colors[3 * oi + 0]) * wn;
                a1 += __ldg(&colors[3 * oi + 1]) * wn;
                a2 += __ldg(&colors[3 * oi + 2]) * wn;
                s_c[warp][k] = make_float2(wn, __int_as_float(oi));
            }
            s_fn[warp] = n;
            out[OFF_DEPTH + p] = ds;
            out[OFF_COLOR + 3 * p + 0] = a0;
            out[OFF_COLOR + 3 * p + 1] = a1;
            out[OFF_COLOR + 3 * p + 2] = a2;
            out[OFF_MASK + p] = (n > 0) ? 1.0f : 0.0f;
        }
    }
    __syncwarp();

    // ---- feature gather: counted loop over compacted list, MLP-friendly ----
    int n = s_fn[warp];
    float fa0 = 0.0f, fa1 = 0.0f;
#pragma unroll 4
    for (int k = 0; k < n; ++k) {
        float2 c = s_c[warp][k];          // LDS.64 broadcast
        float wn = c.x;
        int id = __float_as_int(c.y);
        const float* f = feats + (size_t)id * FDIM;
        fa0 += wn * __ldg(f + lane);
        fa1 += wn * __ldg(f + lane + 32);
    }
    out[OFF_FEAT + (size_t)p * FDIM + lane] = fa0;
    out[OFF_FEAT + (size_t)p * FDIM + lane + 32] = fa1;

    if (fastpath && lane == 0) {
        out[OFF_DEPTH + p] = dsum;
        out[OFF_COLOR + 3 * p + 0] = c0s;
        out[OFF_COLOR + 3 * p + 1] = c1s;
        out[OFF_COLOR + 3 * p + 2] = c2s;
        out[OFF_MASK + p] = anyok ? 1.0f : 0.0f;
    }
}

extern "C" void kernel_launch(void* const* d_in, const int* in_sizes, int n_in,
                              void* d_out, int out_size) {
    const float* pts    = (const float*)d_in[0];
    const float* colors = (const float*)d_in[1];
    const float* feats  = (const float*)d_in[2];
    const float* intr   = (const float*)d_in[3];
    float* out = (float*)d_out;

    void* p_cnt = nullptr;
    cudaGetSymbolAddress(&p_cnt, g_cnt);
    cudaMemsetAsync(p_cnt, 0, sizeof(int) * (NPIX + 1), 0);

    project_bin_kernel<<<NPTS / 256, 256>>>(pts, intr);
    knn_feat_kernel<<<NPIX / 8, 256>>>(colors, feats, out);
}